// round 11
// baseline (speedup 1.0000x reference)
#include <cuda_runtime.h>
#include <cuda_bf16.h>
#include <math.h>
#include <stdint.h>

// ---------------- problem dims ----------------
#define BB    4
#define SS    4096
#define HH    2048
#define VV    32000
#define IDIM  64
#define NLC   8192
#define NROWS (BB * SS)          // 16384
#define K2    192                // split-K: [hi | hi | lo] x [hi | lo | hi]

// ---------------- device scratch ----------------
__device__ int g_winner[NROWS];
__device__ int g_slot[NROWS];
__device__ int g_widx[NROWS];
__device__ int g_count;
__device__ __align__(16) __nv_bfloat16 g_a2 [NLC * K2];   // activations, K-concat split
__device__ __align__(16) __nv_bfloat16 g_b2T[HH * K2];    // Wout^T, K-concat split, [n][k]

// ---------------- helpers ----------------
__device__ __forceinline__ float gelu_exact(float x) {
    return 0.5f * x * (1.0f + erff(x * 0.70710678118654752440f));
}
__device__ __forceinline__ float2 ffma2(float2 a, float2 b, float2 c) {
    unsigned long long ra, rb, rc, rd;
    ra = *reinterpret_cast<unsigned long long*>(&a);
    rb = *reinterpret_cast<unsigned long long*>(&b);
    rc = *reinterpret_cast<unsigned long long*>(&c);
    asm("fma.rn.f32x2 %0, %1, %2, %3;" : "=l"(rd) : "l"(ra), "l"(rb), "l"(rc));
    return *reinterpret_cast<float2*>(&rd);
}

// ---------------- kernel 1a/1b/1c: winner table ----------------
__global__ void k_init() {
    int i = blockIdx.x * blockDim.x + threadIdx.x;
    if (i < NROWS) g_winner[i] = -1;
    if (i == 0) g_count = 0;
}
__global__ void k_winner(const int* __restrict__ pos_b, const int* __restrict__ pos_s) {
    int i = blockIdx.x * blockDim.x + threadIdx.x;
    if (i < NLC) {
        int slot = pos_b[i] * SS + pos_s[i];
        atomicMax(&g_winner[slot], i);   // JAX scatter: last update wins
    }
}
__global__ void k_compact() {
    int i = blockIdx.x * blockDim.x + threadIdx.x;
    if (i < NROWS) {
        int w = g_winner[i];
        if (w >= 0) {
            int p = atomicAdd(&g_count, 1);
            g_slot[p] = i;
            g_widx[p] = w;
        }
    }
}

// ---------------- kernel 2: MLP 1->64->64->64, emit K-concat split-bf16 ----------
#define MLP_E 32
__global__ void __launch_bounds__(256) k_mlp(const float* __restrict__ lc,
                      const float* __restrict__ W0, const float* __restrict__ b0,
                      const float* __restrict__ W1, const float* __restrict__ b1,
                      const float* __restrict__ W2, const float* __restrict__ b2) {
    __shared__ float AT[IDIM][MLP_E + 2];
    __shared__ float Wsh[IDIM * IDIM];
    __shared__ float xsh[MLP_E];

    const int tid = threadIdx.x;
    const int f4  = tid & 15;
    const int eg  = tid >> 4;
    const int j0  = f4 * 4;
    const int e0  = blockIdx.x * MLP_E;

    if (tid < MLP_E) xsh[tid] = lc[e0 + tid];
    {
        const float4* src = reinterpret_cast<const float4*>(W1);
        float4* dst = reinterpret_cast<float4*>(Wsh);
        #pragma unroll
        for (int i = 0; i < 4; i++) dst[tid + 256 * i] = src[tid + 256 * i];
    }
    __syncthreads();

    #pragma unroll
    for (int r = 0; r < 4; r++) {
        int k = j0 + r;
        float w = W0[k], b = b0[k];
        float v0 = gelu_exact(fmaf(xsh[2 * eg],     w, b));
        float v1 = gelu_exact(fmaf(xsh[2 * eg + 1], w, b));
        *reinterpret_cast<float2*>(&AT[k][2 * eg]) = make_float2(v0, v1);
    }
    __syncthreads();

    float2 acc[4];
    {
        float4 bb = *reinterpret_cast<const float4*>(b1 + j0);
        acc[0] = make_float2(bb.x, bb.x); acc[1] = make_float2(bb.y, bb.y);
        acc[2] = make_float2(bb.z, bb.z); acc[3] = make_float2(bb.w, bb.w);
        #pragma unroll 8
        for (int k = 0; k < IDIM; k++) {
            float2 a2 = *reinterpret_cast<float2*>(&AT[k][2 * eg]);
            float4 w4 = *reinterpret_cast<float4*>(&Wsh[k * IDIM + j0]);
            acc[0] = ffma2(a2, make_float2(w4.x, w4.x), acc[0]);
            acc[1] = ffma2(a2, make_float2(w4.y, w4.y), acc[1]);
            acc[2] = ffma2(a2, make_float2(w4.z, w4.z), acc[2]);
            acc[3] = ffma2(a2, make_float2(w4.w, w4.w), acc[3]);
        }
    }
    __syncthreads();

    #pragma unroll
    for (int f = 0; f < 4; f++) {
        *reinterpret_cast<float2*>(&AT[j0 + f][2 * eg]) =
            make_float2(gelu_exact(acc[f].x), gelu_exact(acc[f].y));
    }
    {
        const float4* src = reinterpret_cast<const float4*>(W2);
        float4* dst = reinterpret_cast<float4*>(Wsh);
        #pragma unroll
        for (int i = 0; i < 4; i++) dst[tid + 256 * i] = src[tid + 256 * i];
    }
    __syncthreads();

    {
        float4 bb = *reinterpret_cast<const float4*>(b2 + j0);
        acc[0] = make_float2(bb.x, bb.x); acc[1] = make_float2(bb.y, bb.y);
        acc[2] = make_float2(bb.z, bb.z); acc[3] = make_float2(bb.w, bb.w);
        #pragma unroll 8
        for (int k = 0; k < IDIM; k++) {
            float2 a2 = *reinterpret_cast<float2*>(&AT[k][2 * eg]);
            float4 w4 = *reinterpret_cast<float4*>(&Wsh[k * IDIM + j0]);
            acc[0] = ffma2(a2, make_float2(w4.x, w4.x), acc[0]);
            acc[1] = ffma2(a2, make_float2(w4.y, w4.y), acc[1]);
            acc[2] = ffma2(a2, make_float2(w4.z, w4.z), acc[2]);
            acc[3] = ffma2(a2, make_float2(w4.w, w4.w), acc[3]);
        }
    }

    // emit gelu(h2) as K-concat split: [0,64)=hi, [64,128)=hi, [128,192)=lo
    #pragma unroll
    for (int half = 0; half < 2; half++) {
        float v[4];
        v[0] = gelu_exact(half ? acc[0].y : acc[0].x);
        v[1] = gelu_exact(half ? acc[1].y : acc[1].x);
        v[2] = gelu_exact(half ? acc[2].y : acc[2].x);
        v[3] = gelu_exact(half ? acc[3].y : acc[3].x);
        __nv_bfloat16 h[4], l[4];
        #pragma unroll
        for (int f = 0; f < 4; f++) {
            h[f] = __float2bfloat16(v[f]);
            l[f] = __float2bfloat16(v[f] - __bfloat162float(h[f]));
        }
        size_t rb = (size_t)(e0 + 2 * eg + half) * K2;
        uint2 hb = *reinterpret_cast<uint2*>(h);
        uint2 lb = *reinterpret_cast<uint2*>(l);
        *reinterpret_cast<uint2*>(&g_a2[rb +       j0]) = hb;
        *reinterpret_cast<uint2*>(&g_a2[rb +  64 + j0]) = hb;
        *reinterpret_cast<uint2*>(&g_a2[rb + 128 + j0]) = lb;
    }
}

// ---------------- kernel 2b: split + transpose Wout -> K-concat [n][192] ----------
// layout: [0,64)=hi, [64,128)=lo, [128,192)=hi  (pairs with A's hi,hi,lo)
__global__ void k_wsplit(const float* __restrict__ Wout) {
    int idx = blockIdx.x * blockDim.x + threadIdx.x;   // over HH*IDIM
    if (idx < HH * IDIM) {
        int n = idx >> 6, k = idx & 63;
        float w = Wout[k * HH + n];
        __nv_bfloat16 h = __float2bfloat16(w);
        __nv_bfloat16 l = __float2bfloat16(w - __bfloat162float(h));
        size_t rb = (size_t)n * K2;
        g_b2T[rb +       k] = h;
        g_b2T[rb +  64 + k] = l;
        g_b2T[rb + 128 + k] = h;
    }
}

// ---------------- kernel 3: persistent embedding gather ----------------
#define EMBED_BLOCKS 444
__global__ void __launch_bounds__(256) k_embed(const int* __restrict__ ids,
                                               const float* __restrict__ wte,
                                               float* __restrict__ out) {
    const int lane   = threadIdx.x & 31;
    const int warp   = (blockIdx.x * blockDim.x + threadIdx.x) >> 5;
    const int nwarps = (EMBED_BLOCKS * 256) >> 5;

    for (int row = warp; row < NROWS; row += nwarps) {
        if (g_winner[row] >= 0) continue;
        int id = ids[row];
        id = max(0, min(id, VV - 1));
        const float4* __restrict__ src = reinterpret_cast<const float4*>(wte + (size_t)id * HH);
        float4*       __restrict__ dst = reinterpret_cast<float4*>(out + (size_t)row * HH);
        #pragma unroll
        for (int h = 0; h < 2; h++) {
            float4 v[8];
            #pragma unroll
            for (int i = 0; i < 8; i++) v[i] = src[lane + 32 * (8 * h + i)];
            #pragma unroll
            for (int i = 0; i < 8; i++) __stcs(&dst[lane + 32 * (8 * h + i)], v[i]);
        }
    }
}

// ---------------- kernel 4: HMMA GEMM [count x 192] @ [192 x 2048] + scatter ----------
// mma.sync.aligned.m16n8k16 bf16, fp32 accum. Block = 8 warps; warp w owns rows
// m0 + 16w .. +15 across a 64-col n-tile. No shared memory — fragments straight
// from L1/L2 (A2 = 3.1 MB, B2T = 786 KB; both L2-resident).
__global__ void __launch_bounds__(256) k_gemm_mma(const float* __restrict__ bout,
                                                  float* __restrict__ out) {
    const int count = g_count;
    const int m0 = blockIdx.y * 128;
    if (m0 >= count) return;
    const int n0 = blockIdx.x * 64;

    const int wid  = threadIdx.x >> 5;
    const int lane = threadIdx.x & 31;
    const int grow = lane >> 2;          // 0..7
    const int kq   = (lane & 3) * 2;     // 0,2,4,6

    const int rA  = m0 + wid * 16 + grow;
    const int rA8 = rA + 8;
    const __nv_bfloat16* pA  = g_a2 + (size_t)((rA  < count) ? g_widx[rA]  : 0) * K2;
    const __nv_bfloat16* pA8 = g_a2 + (size_t)((rA8 < count) ? g_widx[rA8] : 0) * K2;
    const __nv_bfloat16* pB  = g_b2T + (size_t)(n0 + grow) * K2;   // + ns*8*K2 per subtile

    float acc[8][4];
    #pragma unroll
    for (int ns = 0; ns < 8; ns++)
        #pragma unroll
        for (int c = 0; c < 4; c++) acc[ns][c] = 0.f;

    #pragma unroll
    for (int ks = 0; ks < K2 / 16; ks++) {        // 12 k-steps
        const int kb = ks * 16 + kq;
        uint32_t a0 = *reinterpret_cast<const uint32_t*>(pA  + kb);
        uint32_t a1 = *reinterpret_cast<const uint32_t*>(pA8 + kb);
        uint32_t a2 = *reinterpret_cast<const uint32_t*>(pA  + kb + 8);
        uint32_t a3 = *reinterpret_cast<const uint32_t*>(pA8 + kb + 8);
        #pragma unroll
        for (int ns = 0; ns < 8; ns++) {
            const __nv_bfloat16* pBc = pB + (size_t)ns * 8 * K2;
            uint32_t b0 = *reinterpret_cast<const uint32_t*>(pBc + kb);
            uint32_t b1 = *reinterpret_cast<const uint32_t*>(pBc + kb + 8);
            asm volatile(
                "mma.sync.aligned.m16n8k16.row.col.f32.bf16.bf16.f32 "
                "{%0,%1,%2,%3}, {%4,%5,%6,%7}, {%8,%9}, {%0,%1,%2,%3};"
                : "+f"(acc[ns][0]), "+f"(acc[ns][1]), "+f"(acc[ns][2]), "+f"(acc[ns][3])
                : "r"(a0), "r"(a1), "r"(a2), "r"(a3), "r"(b0), "r"(b1));
        }
    }

    // epilogue: c0,c1 -> row rA cols (kq,kq+1); c2,c3 -> row rA8 same cols
    const int slotA  = (rA  < count) ? g_slot[rA]  : -1;
    const int slotA8 = (rA8 < count) ? g_slot[rA8] : -1;
    #pragma unroll
    for (int ns = 0; ns < 8; ns++) {
        int col = n0 + ns * 8 + kq;
        float2 bv = *reinterpret_cast<const float2*>(bout + col);
        if (slotA >= 0) {
            float2 v = make_float2(acc[ns][0] + bv.x, acc[ns][1] + bv.y);
            *reinterpret_cast<float2*>(out + (size_t)slotA * HH + col) = v;
        }
        if (slotA8 >= 0) {
            float2 v = make_float2(acc[ns][2] + bv.x, acc[ns][3] + bv.y);
            *reinterpret_cast<float2*>(out + (size_t)slotA8 * HH + col) = v;
        }
    }
}

// ---------------- streams/events ----------------
static cudaStream_t s_mlp = nullptr, s_embed = nullptr;
static cudaEvent_t ev_start, ev_winner, ev_mlp, ev_embed;
namespace {
struct HxInit {
    HxInit() {
        cudaStreamCreateWithFlags(&s_mlp,   cudaStreamNonBlocking);
        cudaStreamCreateWithFlags(&s_embed, cudaStreamNonBlocking);
        cudaEventCreateWithFlags(&ev_start,  cudaEventDisableTiming);
        cudaEventCreateWithFlags(&ev_winner, cudaEventDisableTiming);
        cudaEventCreateWithFlags(&ev_mlp,    cudaEventDisableTiming);
        cudaEventCreateWithFlags(&ev_embed,  cudaEventDisableTiming);
    }
};
HxInit hx_init_;
}

// ---------------- launcher ----------------
extern "C" void kernel_launch(void* const* d_in, const int* in_sizes, int n_in,
                              void* d_out, int out_size) {
    const int*   input_ids = (const int*)  d_in[0];
    const float* lc        = (const float*)d_in[1];
    const int*   pos_b     = (const int*)  d_in[2];
    const int*   pos_s     = (const int*)  d_in[3];
    const float* wte       = (const float*)d_in[4];
    const float* W0        = (const float*)d_in[5];
    const float* b0        = (const float*)d_in[6];
    const float* W1        = (const float*)d_in[7];
    const float* b1        = (const float*)d_in[8];
    const float* W2        = (const float*)d_in[9];
    const float* b2        = (const float*)d_in[10];
    const float* Wout      = (const float*)d_in[11];
    const float* bout      = (const float*)d_in[12];
    float* out = (float*)d_out;

    // fork: MLP + weight split (independent of winner table)
    cudaEventRecord(ev_start, 0);
    cudaStreamWaitEvent(s_mlp, ev_start, 0);
    k_mlp   <<<NLC / MLP_E, 256, 0, s_mlp>>>(lc, W0, b0, W1, b1, W2, b2);
    k_wsplit<<<(HH * IDIM) / 256, 256, 0, s_mlp>>>(Wout);
    cudaEventRecord(ev_mlp, s_mlp);

    // main: winner table
    k_init  <<<NROWS / 256, 256>>>();
    k_winner<<<NLC   / 256, 256>>>(pos_b, pos_s);
    cudaEventRecord(ev_winner, 0);

    // fork: persistent DRAM-bound embed; tensor-bound gemm co-schedules around it
    cudaStreamWaitEvent(s_embed, ev_winner, 0);
    k_embed<<<EMBED_BLOCKS, 256, 0, s_embed>>>(input_ids, wte, out);
    cudaEventRecord(ev_embed, s_embed);

    // main: compact, then tensor-core GEMM
    k_compact<<<NROWS / 256, 256>>>();
    cudaStreamWaitEvent(0, ev_mlp, 0);
    k_gemm_mma<<<dim3(HH / 64, NLC / 128), 256>>>(bout, out);

    cudaStreamWaitEvent(0, ev_embed, 0);
}

// round 12
// speedup vs baseline: 1.6776x; 1.6776x over previous
#include <cuda_runtime.h>
#include <cuda_bf16.h>
#include <math.h>
#include <stdint.h>

// ---------------- problem dims ----------------
#define BB    4
#define SS    4096
#define HH    2048
#define VV    32000
#define IDIM  64
#define NLC   8192
#define NROWS (BB * SS)          // 16384
#define K2    192                // split-K concat: A=[hi|hi|lo], B=[hi|lo|hi]

// ---------------- device scratch ----------------
__device__ int g_winner[NROWS];
__device__ int g_slot[NROWS];
__device__ int g_widx[NROWS];
__device__ int g_count;
__device__ __align__(16) __nv_bfloat16 g_a2 [NLC * K2];   // activations, K-concat split
__device__ __align__(16) __nv_bfloat16 g_b2T[HH * K2];    // Wout^T, K-concat split, [n][k]

// ---------------- helpers ----------------
__device__ __forceinline__ float gelu_exact(float x) {
    return 0.5f * x * (1.0f + erff(x * 0.70710678118654752440f));
}
__device__ __forceinline__ float2 ffma2(float2 a, float2 b, float2 c) {
    unsigned long long ra, rb, rc, rd;
    ra = *reinterpret_cast<unsigned long long*>(&a);
    rb = *reinterpret_cast<unsigned long long*>(&b);
    rc = *reinterpret_cast<unsigned long long*>(&c);
    asm("fma.rn.f32x2 %0, %1, %2, %3;" : "=l"(rd) : "l"(ra), "l"(rb), "l"(rc));
    return *reinterpret_cast<float2*>(&rd);
}
__device__ __forceinline__ uint32_t smem_u32(const void* p) {
    uint32_t a;
    asm("{ .reg .u64 t; cvta.to.shared.u64 t, %1; cvt.u32.u64 %0, t; }" : "=r"(a) : "l"(p));
    return a;
}
__device__ __forceinline__ void ldm_x4(uint32_t* r, uint32_t addr) {
    asm volatile("ldmatrix.sync.aligned.m8n8.x4.shared.b16 {%0,%1,%2,%3}, [%4];"
        : "=r"(r[0]), "=r"(r[1]), "=r"(r[2]), "=r"(r[3]) : "r"(addr));
}
__device__ __forceinline__ void mma16816(float* c, const uint32_t* a, uint32_t b0, uint32_t b1) {
    asm volatile("mma.sync.aligned.m16n8k16.row.col.f32.bf16.bf16.f32 "
        "{%0,%1,%2,%3}, {%4,%5,%6,%7}, {%8,%9}, {%0,%1,%2,%3};"
        : "+f"(c[0]), "+f"(c[1]), "+f"(c[2]), "+f"(c[3])
        : "r"(a[0]), "r"(a[1]), "r"(a[2]), "r"(a[3]), "r"(b0), "r"(b1));
}

// ---------------- winner table ----------------
__global__ void k_init() {
    int i = blockIdx.x * blockDim.x + threadIdx.x;
    if (i < NROWS) g_winner[i] = -1;
    if (i == 0) g_count = 0;
}
__global__ void k_winner(const int* __restrict__ pos_b, const int* __restrict__ pos_s) {
    int i = blockIdx.x * blockDim.x + threadIdx.x;
    if (i < NLC) {
        int slot = pos_b[i] * SS + pos_s[i];
        atomicMax(&g_winner[slot], i);   // JAX scatter: last update wins
    }
}
__global__ void k_compact() {
    int i = blockIdx.x * blockDim.x + threadIdx.x;
    if (i < NROWS) {
        int w = g_winner[i];
        if (w >= 0) {
            int p = atomicAdd(&g_count, 1);
            g_slot[p] = i;
            g_widx[p] = w;
        }
    }
}

// ---------------- MLP 1->64->64->64, emit K-concat split-bf16 ----------
#define MLP_E 32
__global__ void __launch_bounds__(256) k_mlp(const float* __restrict__ lc,
                      const float* __restrict__ W0, const float* __restrict__ b0,
                      const float* __restrict__ W1, const float* __restrict__ b1,
                      const float* __restrict__ W2, const float* __restrict__ b2) {
    __shared__ float AT[IDIM][MLP_E + 2];
    __shared__ float Wsh[IDIM * IDIM];
    __shared__ float xsh[MLP_E];

    const int tid = threadIdx.x;
    const int f4  = tid & 15;
    const int eg  = tid >> 4;
    const int j0  = f4 * 4;
    const int e0  = blockIdx.x * MLP_E;

    if (tid < MLP_E) xsh[tid] = lc[e0 + tid];
    {
        const float4* src = reinterpret_cast<const float4*>(W1);
        float4* dst = reinterpret_cast<float4*>(Wsh);
        #pragma unroll
        for (int i = 0; i < 4; i++) dst[tid + 256 * i] = src[tid + 256 * i];
    }
    __syncthreads();

    #pragma unroll
    for (int r = 0; r < 4; r++) {
        int k = j0 + r;
        float w = W0[k], b = b0[k];
        float v0 = gelu_exact(fmaf(xsh[2 * eg],     w, b));
        float v1 = gelu_exact(fmaf(xsh[2 * eg + 1], w, b));
        *reinterpret_cast<float2*>(&AT[k][2 * eg]) = make_float2(v0, v1);
    }
    __syncthreads();

    float2 acc[4];
    {
        float4 bb = *reinterpret_cast<const float4*>(b1 + j0);
        acc[0] = make_float2(bb.x, bb.x); acc[1] = make_float2(bb.y, bb.y);
        acc[2] = make_float2(bb.z, bb.z); acc[3] = make_float2(bb.w, bb.w);
        #pragma unroll 8
        for (int k = 0; k < IDIM; k++) {
            float2 a2 = *reinterpret_cast<float2*>(&AT[k][2 * eg]);
            float4 w4 = *reinterpret_cast<float4*>(&Wsh[k * IDIM + j0]);
            acc[0] = ffma2(a2, make_float2(w4.x, w4.x), acc[0]);
            acc[1] = ffma2(a2, make_float2(w4.y, w4.y), acc[1]);
            acc[2] = ffma2(a2, make_float2(w4.z, w4.z), acc[2]);
            acc[3] = ffma2(a2, make_float2(w4.w, w4.w), acc[3]);
        }
    }
    __syncthreads();

    #pragma unroll
    for (int f = 0; f < 4; f++) {
        *reinterpret_cast<float2*>(&AT[j0 + f][2 * eg]) =
            make_float2(gelu_exact(acc[f].x), gelu_exact(acc[f].y));
    }
    {
        const float4* src = reinterpret_cast<const float4*>(W2);
        float4* dst = reinterpret_cast<float4*>(Wsh);
        #pragma unroll
        for (int i = 0; i < 4; i++) dst[tid + 256 * i] = src[tid + 256 * i];
    }
    __syncthreads();

    {
        float4 bb = *reinterpret_cast<const float4*>(b2 + j0);
        acc[0] = make_float2(bb.x, bb.x); acc[1] = make_float2(bb.y, bb.y);
        acc[2] = make_float2(bb.z, bb.z); acc[3] = make_float2(bb.w, bb.w);
        #pragma unroll 8
        for (int k = 0; k < IDIM; k++) {
            float2 a2 = *reinterpret_cast<float2*>(&AT[k][2 * eg]);
            float4 w4 = *reinterpret_cast<float4*>(&Wsh[k * IDIM + j0]);
            acc[0] = ffma2(a2, make_float2(w4.x, w4.x), acc[0]);
            acc[1] = ffma2(a2, make_float2(w4.y, w4.y), acc[1]);
            acc[2] = ffma2(a2, make_float2(w4.z, w4.z), acc[2]);
            acc[3] = ffma2(a2, make_float2(w4.w, w4.w), acc[3]);
        }
    }

    // emit gelu(h2) as K-concat split: [0,64)=hi, [64,128)=hi, [128,192)=lo
    #pragma unroll
    for (int half = 0; half < 2; half++) {
        float v[4];
        v[0] = gelu_exact(half ? acc[0].y : acc[0].x);
        v[1] = gelu_exact(half ? acc[1].y : acc[1].x);
        v[2] = gelu_exact(half ? acc[2].y : acc[2].x);
        v[3] = gelu_exact(half ? acc[3].y : acc[3].x);
        __nv_bfloat16 h[4], l[4];
        #pragma unroll
        for (int f = 0; f < 4; f++) {
            h[f] = __float2bfloat16(v[f]);
            l[f] = __float2bfloat16(v[f] - __bfloat162float(h[f]));
        }
        size_t rb = (size_t)(e0 + 2 * eg + half) * K2;
        uint2 hb = *reinterpret_cast<uint2*>(h);
        uint2 lb = *reinterpret_cast<uint2*>(l);
        *reinterpret_cast<uint2*>(&g_a2[rb +       j0]) = hb;
        *reinterpret_cast<uint2*>(&g_a2[rb +  64 + j0]) = hb;
        *reinterpret_cast<uint2*>(&g_a2[rb + 128 + j0]) = lb;
    }
}

// ---------------- split + transpose Wout -> K-concat [n][192] ----------
// layout: [0,64)=hi, [64,128)=lo, [128,192)=hi  (pairs with A's hi,hi,lo)
__global__ void k_wsplit(const float* __restrict__ Wout) {
    int idx = blockIdx.x * blockDim.x + threadIdx.x;   // over HH*IDIM
    if (idx < HH * IDIM) {
        int n = idx >> 6, k = idx & 63;
        float w = Wout[k * HH + n];
        __nv_bfloat16 h = __float2bfloat16(w);
        __nv_bfloat16 l = __float2bfloat16(w - __bfloat162float(h));
        size_t rb = (size_t)n * K2;
        g_b2T[rb +       k] = h;
        g_b2T[rb +  64 + k] = l;
        g_b2T[rb + 128 + k] = h;
    }
}

// ---------------- persistent embedding gather ----------------
#define EMBED_BLOCKS 444
__global__ void __launch_bounds__(256) k_embed(const int* __restrict__ ids,
                                               const float* __restrict__ wte,
                                               float* __restrict__ out) {
    const int lane   = threadIdx.x & 31;
    const int warp   = (blockIdx.x * blockDim.x + threadIdx.x) >> 5;
    const int nwarps = (EMBED_BLOCKS * 256) >> 5;

    for (int row = warp; row < NROWS; row += nwarps) {
        if (g_winner[row] >= 0) continue;
        int id = ids[row];
        id = max(0, min(id, VV - 1));
        const float4* __restrict__ src = reinterpret_cast<const float4*>(wte + (size_t)id * HH);
        float4*       __restrict__ dst = reinterpret_cast<float4*>(out + (size_t)row * HH);
        #pragma unroll
        for (int h = 0; h < 2; h++) {
            float4 v[8];
            #pragma unroll
            for (int i = 0; i < 8; i++) v[i] = src[lane + 32 * (8 * h + i)];
            #pragma unroll
            for (int i = 0; i < 8; i++) __stcs(&dst[lane + 32 * (8 * h + i)], v[i]);
        }
    }
}

// ---------------- HMMA GEMM [count x 192] @ [192 x 2048] + scatter ----------
// Tile 128m x 128n x 192k, smem-staged, ldmatrix.x4 fragments.
// 8 warps = 4 m-groups x 2 n-groups; warp tile = 32m x 64n.
// Smem row stride 200 bf16 (400B): ldmatrix rows hit distinct quad-banks.
#define GS_STRIDE 200
#define GEMM_SMEM (2 * 128 * GS_STRIDE * 2)   // A + B = 102400 B
extern __shared__ __nv_bfloat16 gsm2[];

__global__ void __launch_bounds__(256) k_gemm_mma(const float* __restrict__ bout,
                                                  float* __restrict__ out) {
    const int count = g_count;
    const int m0 = blockIdx.y * 128;
    if (m0 >= count) return;
    const int n0 = blockIdx.x * 128;
    const int tid = threadIdx.x;

    __nv_bfloat16* As = gsm2;
    __nv_bfloat16* Bs = gsm2 + 128 * GS_STRIDE;

    // ---- stage A (gathered rows) and B: thread t -> row t>>1, half t&1, 12 uint4 ----
    {
        int r = tid >> 1, h = tid & 1;
        int row = m0 + r;
        const uint4* srcA = nullptr;
        if (row < count)
            srcA = reinterpret_cast<const uint4*>(g_a2 + (size_t)g_widx[row] * K2) + h * 12;
        uint4* dstA = reinterpret_cast<uint4*>(As + r * GS_STRIDE + h * 96);
        const uint4* srcB = reinterpret_cast<const uint4*>(g_b2T + (size_t)(n0 + r) * K2) + h * 12;
        uint4* dstB = reinterpret_cast<uint4*>(Bs + r * GS_STRIDE + h * 96);
        #pragma unroll
        for (int c = 0; c < 12; c++) {
            dstA[c] = srcA ? srcA[c] : make_uint4(0u, 0u, 0u, 0u);
            dstB[c] = srcB[c];
        }
    }
    __syncthreads();

    const int wid  = tid >> 5;
    const int lane = tid & 31;
    const int mg   = wid & 3;        // m-group: rows mg*32 .. +31
    const int ng   = wid >> 2;       // n-group: cols ng*64 .. +63

    // ldmatrix lane addresses (bytes)
    // A x4: matrices (m0-7,k0)(m8-15,k0)(m0-7,k8)(m8-15,k8): row=(lane&15), coloff=(lane>>4)*8
    uint32_t aAddr = smem_u32(As) +
        (uint32_t)(((mg * 32 + (lane & 15)) * GS_STRIDE + (lane >> 4) * 8) * 2);
    // B x4: matrices (n0-7,k0)(n0-7,k8)(n8-15,k0)(n8-15,k8):
    //   row = (lane&7) + ((lane>>4)<<3), coloff = ((lane>>3)&1)*8
    uint32_t bAddr = smem_u32(Bs) +
        (uint32_t)(((ng * 64 + (lane & 7) + ((lane >> 4) << 3)) * GS_STRIDE +
                    (((lane >> 3) & 1) << 3)) * 2);

    float acc[2][8][4];
    #pragma unroll
    for (int am = 0; am < 2; am++)
        #pragma unroll
        for (int ns = 0; ns < 8; ns++)
            #pragma unroll
            for (int c = 0; c < 4; c++) acc[am][ns][c] = 0.f;

    #pragma unroll 1
    for (int ks = 0; ks < K2 / 16; ks++) {         // 12 k-steps
        uint32_t aF0[4], aF1[4], bF[4][4];
        ldm_x4(aF0, aAddr);
        ldm_x4(aF1, aAddr + 16 * GS_STRIDE * 2);
        #pragma unroll
        for (int p = 0; p < 4; p++) ldm_x4(bF[p], bAddr + p * 16 * GS_STRIDE * 2);
        aAddr += 32;                                // 16 bf16 columns
        bAddr += 32;
        #pragma unroll
        for (int p = 0; p < 4; p++) {
            // bF[p] = {b0(ns=2p), b1(2p), b0(2p+1), b1(2p+1)}
            mma16816(acc[0][2 * p],     aF0, bF[p][0], bF[p][1]);
            mma16816(acc[0][2 * p + 1], aF0, bF[p][2], bF[p][3]);
            mma16816(acc[1][2 * p],     aF1, bF[p][0], bF[p][1]);
            mma16816(acc[1][2 * p + 1], aF1, bF[p][2], bF[p][3]);
        }
    }

    // ---- epilogue: scatter rows via g_slot, add bias ----
    #pragma unroll
    for (int am = 0; am < 2; am++) {
        int r = m0 + mg * 32 + am * 16 + (lane >> 2);
        int s0 = (r     < count) ? g_slot[r]     : -1;
        int s1 = (r + 8 < count) ? g_slot[r + 8] : -1;
        #pragma unroll
        for (int ns = 0; ns < 8; ns++) {
            int col = n0 + ng * 64 + ns * 8 + (lane & 3) * 2;
            float2 bv = *reinterpret_cast<const float2*>(bout + col);
            if (s0 >= 0) {
                float2 v = make_float2(acc[am][ns][0] + bv.x, acc[am][ns][1] + bv.y);
                *reinterpret_cast<float2*>(out + (size_t)s0 * HH + col) = v;
            }
            if (s1 >= 0) {
                float2 v = make_float2(acc[am][ns][2] + bv.x, acc[am][ns][3] + bv.y);
                *reinterpret_cast<float2*>(out + (size_t)s1 * HH + col) = v;
            }
        }
    }
}

// ---------------- streams/events ----------------
static cudaStream_t s_mlp = nullptr, s_embed = nullptr;
static cudaEvent_t ev_start, ev_winner, ev_mlp, ev_embed;
namespace {
struct HxInit {
    HxInit() {
        cudaStreamCreateWithFlags(&s_mlp,   cudaStreamNonBlocking);
        cudaStreamCreateWithFlags(&s_embed, cudaStreamNonBlocking);
        cudaEventCreateWithFlags(&ev_start,  cudaEventDisableTiming);
        cudaEventCreateWithFlags(&ev_winner, cudaEventDisableTiming);
        cudaEventCreateWithFlags(&ev_mlp,    cudaEventDisableTiming);
        cudaEventCreateWithFlags(&ev_embed,  cudaEventDisableTiming);
        cudaFuncSetAttribute(k_gemm_mma, cudaFuncAttributeMaxDynamicSharedMemorySize, GEMM_SMEM);
    }
};
HxInit hx_init_;
}

// ---------------- launcher ----------------
extern "C" void kernel_launch(void* const* d_in, const int* in_sizes, int n_in,
                              void* d_out, int out_size) {
    const int*   input_ids = (const int*)  d_in[0];
    const float* lc        = (const float*)d_in[1];
    const int*   pos_b     = (const int*)  d_in[2];
    const int*   pos_s     = (const int*)  d_in[3];
    const float* wte       = (const float*)d_in[4];
    const float* W0        = (const float*)d_in[5];
    const float* b0        = (const float*)d_in[6];
    const float* W1        = (const float*)d_in[7];
    const float* b1        = (const float*)d_in[8];
    const float* W2        = (const float*)d_in[9];
    const float* b2        = (const float*)d_in[10];
    const float* Wout      = (const float*)d_in[11];
    const float* bout      = (const float*)d_in[12];
    float* out = (float*)d_out;

    // fork: MLP + weight split (independent of winner table)
    cudaEventRecord(ev_start, 0);
    cudaStreamWaitEvent(s_mlp, ev_start, 0);
    k_mlp   <<<NLC / MLP_E, 256, 0, s_mlp>>>(lc, W0, b0, W1, b1, W2, b2);
    k_wsplit<<<(HH * IDIM) / 256, 256, 0, s_mlp>>>(Wout);
    cudaEventRecord(ev_mlp, s_mlp);

    // main: winner table
    k_init  <<<NROWS / 256, 256>>>();
    k_winner<<<NLC   / 256, 256>>>(pos_b, pos_s);
    cudaEventRecord(ev_winner, 0);

    // fork: persistent DRAM-bound embed; tensor-bound gemm co-schedules around it
    cudaStreamWaitEvent(s_embed, ev_winner, 0);
    k_embed<<<EMBED_BLOCKS, 256, 0, s_embed>>>(input_ids, wte, out);
    cudaEventRecord(ev_embed, s_embed);

    // main: compact, then tensor-core GEMM
    k_compact<<<NROWS / 256, 256>>>();
    cudaStreamWaitEvent(0, ev_mlp, 0);
    k_gemm_mma<<<dim3(HH / 128, NLC / 128), 256, GEMM_SMEM>>>(bout, out);

    cudaStreamWaitEvent(0, ev_embed, 0);
}